// round 15
// baseline (speedup 1.0000x reference)
#include <cuda_runtime.h>
#include <cuda_fp16.h>
#include <mma.h>
#include <math.h>
#include <cstdint>

using namespace nvcuda;

#define BATCH    2
#define SEQ      2048
#define HIDDEN   1024
#define HEADS    16
#define HEAD_DIM 64
#define MTOT     (BATCH*SEQ)      // 4096
#define BHN      (BATCH*HEADS)    // 32
#define HH       (HIDDEN*HIDDEN)

// scratch (allocation-free rule: __device__ globals)
static __device__ __half g_xh[MTOT*HIDDEN];        // X in fp16
static __device__ __half g_wh[4*HH];               // Wq,Wk,Wv,Wo in fp16
static __device__ float  g_rt[SEQ*64];             // rope: [s][0:32)=cos,[32:64)=sin
static __device__ __half g_q [BHN*SEQ*HEAD_DIM];   // [B,H,S,D] fp16 (q scaled by 1/8*log2e)
static __device__ __half g_k [BHN*SEQ*HEAD_DIM];
static __device__ __half g_v [BHN*SEQ*HEAD_DIM];
static __device__ __half g_ao[MTOT*HIDDEN];        // attention out fp16

// ---------------------------------------------------------------------------
// helpers
// ---------------------------------------------------------------------------
__device__ __forceinline__ void cp16(uint32_t dst, const void* src) {
    asm volatile("cp.async.cg.shared.global [%0], [%1], 16;" :: "r"(dst), "l"(src));
}
__device__ __forceinline__ void cp_commit() {
    asm volatile("cp.async.commit_group;" ::: "memory");
}
__device__ __forceinline__ void cp_wait0() {
    asm volatile("cp.async.wait_group 0;" ::: "memory");
}
__device__ __forceinline__ void cp_wait1() {
    asm volatile("cp.async.wait_group 1;" ::: "memory");
}
__device__ __forceinline__ uint32_t sm_u32(const void* p) {
    return (uint32_t)__cvta_generic_to_shared(p);
}
__device__ __forceinline__ uint32_t pack_h2(float lo, float hi) {
    __half2 h = __floats2half2_rn(lo, hi);
    return *reinterpret_cast<uint32_t*>(&h);
}
__device__ __forceinline__ float ex2(float x) {
    float y;
    asm("ex2.approx.ftz.f32 %0, %1;" : "=f"(y) : "f"(x));
    return y;
}
__device__ __forceinline__ uint32_t ex2_h2(uint32_t x) {
    uint32_t y;
    asm("ex2.approx.f16x2 %0, %1;" : "=r"(y) : "r"(x));
    return y;
}
__device__ __forceinline__ void mma16(float d[4], const uint32_t a[4],
                                      uint32_t b0, uint32_t b1)
{
    asm volatile(
        "mma.sync.aligned.m16n8k16.row.col.f32.f16.f16.f32 "
        "{%0,%1,%2,%3}, {%4,%5,%6,%7}, {%8,%9}, {%0,%1,%2,%3};"
        : "+f"(d[0]), "+f"(d[1]), "+f"(d[2]), "+f"(d[3])
        : "r"(a[0]), "r"(a[1]), "r"(a[2]), "r"(a[3]), "r"(b0), "r"(b1));
}
__device__ __forceinline__ void ldsm_x4(uint32_t& r0, uint32_t& r1,
                                        uint32_t& r2, uint32_t& r3, uint32_t addr) {
    asm volatile("ldmatrix.sync.aligned.m8n8.x4.shared.b16 {%0,%1,%2,%3}, [%4];"
                 : "=r"(r0), "=r"(r1), "=r"(r2), "=r"(r3) : "r"(addr));
}
__device__ __forceinline__ void ldsm_x4_t(uint32_t& r0, uint32_t& r1,
                                          uint32_t& r2, uint32_t& r3, uint32_t addr) {
    asm volatile("ldmatrix.sync.aligned.m8n8.x4.trans.shared.b16 {%0,%1,%2,%3}, [%4];"
                 : "=r"(r0), "=r"(r1), "=r"(r2), "=r"(r3) : "r"(addr));
}

// ---------------------------------------------------------------------------
// setup: fp16 conversion + rope table (merged, one launch)
// ---------------------------------------------------------------------------
#define XN4 (MTOT*HIDDEN/4)       // 1048576
#define WN4 (HH/4)                // 262144
#define CONVN (XN4 + 4*WN4)       // 2097152
__global__ void conv_kernel(const float* __restrict__ X,
                            const float* __restrict__ Wq,
                            const float* __restrict__ Wk,
                            const float* __restrict__ Wv,
                            const float* __restrict__ Wo)
{
    int gid = blockIdx.x * blockDim.x + threadIdx.x;
    if (gid < CONVN) {
        const float4* s4; __half2* d2;
        if (gid < XN4) {
            s4 = (const float4*)X + gid;
            d2 = (__half2*)g_xh + (size_t)gid * 2;
        } else {
            int w = gid - XN4;
            int sel = w >> 18;          // WN4 = 2^18
            int off = w & (WN4 - 1);
            const float* W = (sel == 0) ? Wq : (sel == 1) ? Wk : (sel == 2) ? Wv : Wo;
            s4 = (const float4*)W + off;
            d2 = (__half2*)g_wh + ((size_t)sel * WN4 + off) * 2;
        }
        float4 v = *s4;
        d2[0] = __floats2half2_rn(v.x, v.y);
        d2[1] = __floats2half2_rn(v.z, v.w);
    } else {
        int t = gid - CONVN;            // < SEQ*32
        int i = t & 31, s = t >> 5;
        float inv = powf(10000.0f, -(float)i * (1.0f / 32.0f));
        float c, sn;
        sincosf((float)s * inv, &sn, &c);
        g_rt[s * 64 + i]      = c;
        g_rt[s * 64 + 32 + i] = sn;
    }
}

// ---------------------------------------------------------------------------
// fp16 wmma GEMM (qkv): C(128x128) = A(128xK)*W(128xK)^T, K=1024, BK=64.
// 3-stage cp.async pipeline, ONE __syncthreads per iteration (16 iters).
// 8 warps: wm=wid&3 (32 rows), wn=wid>>2 (64 cols).
// ---------------------------------------------------------------------------
#define LDAH 72                   // halves; 144B row stride (ldsm conflict-free)
#define STGH (2*128*LDAH)         // halves per stage (A+W) = 18432
#define LDC  132

using HFragA = wmma::fragment<wmma::matrix_a, 16, 16, 16, __half, wmma::row_major>;
using HFragB = wmma::fragment<wmma::matrix_b, 16, 16, 16, __half, wmma::col_major>;
using HFragC = wmma::fragment<wmma::accumulator, 16, 16, 16, float>;

__device__ __forceinline__ void hgemm_issue(const __half* __restrict__ A,
                                            const __half* __restrict__ W,
                                            __half* sm, int kb, int s, int tid)
{
    __half* As = sm + s * STGH;
    __half* Ws = As + 128 * LDAH;
#pragma unroll
    for (int i = 0; i < 4; i++) {
        int idx = tid + i * 256;            // 0..1023
        int r = idx >> 3, c = (idx & 7) * 8;
        cp16(sm_u32(As + r * LDAH + c), A + (size_t)r * HIDDEN + kb * 64 + c);
        cp16(sm_u32(Ws + r * LDAH + c), W + (size_t)r * HIDDEN + kb * 64 + c);
    }
    cp_commit();
}

__device__ __forceinline__ void hgemm_mainloop(const __half* __restrict__ A,
                                               const __half* __restrict__ W,
                                               __half* sm, HFragC acc[2][4],
                                               int wm, int wn)
{
    const int tid = threadIdx.x;
#pragma unroll
    for (int mi = 0; mi < 2; mi++)
#pragma unroll
        for (int ni = 0; ni < 4; ni++)
            wmma::fill_fragment(acc[mi][ni], 0.0f);

    hgemm_issue(A, W, sm, 0, 0, tid);
    hgemm_issue(A, W, sm, 1, 1, tid);

    for (int kb = 0; kb < 16; kb++) {
        int s = kb % 3;
        if (kb < 15) cp_wait1(); else cp_wait0();
        __syncthreads();
        if (kb + 2 < 16) hgemm_issue(A, W, sm, kb + 2, (kb + 2) % 3, tid);

        __half* As = sm + s * STGH;
        __half* Ws = As + 128 * LDAH;
#pragma unroll
        for (int kk = 0; kk < 64; kk += 16) {
            HFragA af[2];
            HFragB bf[4];
#pragma unroll
            for (int mi = 0; mi < 2; mi++)
                wmma::load_matrix_sync(af[mi], &As[(wm * 32 + mi * 16) * LDAH + kk], LDAH);
#pragma unroll
            for (int ni = 0; ni < 4; ni++)
                wmma::load_matrix_sync(bf[ni], &Ws[(wn * 64 + ni * 16) * LDAH + kk], LDAH);
#pragma unroll
            for (int mi = 0; mi < 2; mi++)
#pragma unroll
                for (int ni = 0; ni < 4; ni++)
                    wmma::mma_sync(acc[mi][ni], af[mi], bf[ni], acc[mi][ni]);
        }
    }
    __syncthreads();   // before epilogue reuses smem
}

__device__ __forceinline__ void stage_C(float* Cs, HFragC acc[2][4], int wm, int wn)
{
#pragma unroll
    for (int mi = 0; mi < 2; mi++)
#pragma unroll
        for (int ni = 0; ni < 4; ni++)
            wmma::store_matrix_sync(Cs + (wm * 32 + mi * 16) * LDC + wn * 64 + ni * 16,
                                    acc[mi][ni], LDC, wmma::mem_row_major);
}

// ---------------------------------------------------------------------------
// QKV projection + bias + RoPE fused epilogue -> fp16. grid (8, 32, 3).
// ---------------------------------------------------------------------------
__global__ void __launch_bounds__(256, 2)
qkv_mma(const float* __restrict__ bq,
        const float* __restrict__ bk,
        const float* __restrict__ bv)
{
    extern __shared__ char smraw[];
    const int tid = threadIdx.x, wid = tid >> 5;
    const int wm = wid & 3, wn = wid >> 2;
    const int m0 = blockIdx.y * 128, n0 = blockIdx.x * 128;
    const int z = blockIdx.z;

    const __half* W = g_wh + (size_t)z * HH;
    const float* bias = (z == 0) ? bq : (z == 1) ? bk : bv;
    __half* dst = (z == 0) ? g_q : (z == 1) ? g_k : g_v;

    HFragC acc[2][4];
    hgemm_mainloop(g_xh + (size_t)m0 * HIDDEN, W + (size_t)n0 * HIDDEN,
                   (__half*)smraw, acc, wm, wn);

    float* Cs = (float*)smraw;
    stage_C(Cs, acc, wm, wn);
    __syncthreads();

    const int r = tid >> 1, hh = tid & 1;
    const int m = m0 + r;
    const int b = m >> 11, s = m & (SEQ - 1);
    const int h = (n0 >> 6) + hh;
    const float* crow = Cs + r * LDC + hh * 64;
    const float* brow = bias + n0 + hh * 64;
    __half* drow = dst + (((size_t)(b * HEADS + h)) * SEQ + s) * HEAD_DIM;

    if (z < 2) {
        const float* rt = g_rt + s * 64;
        const float scale = (z == 0) ? 0.125f * 1.44269504088896f : 1.0f;
#pragma unroll
        for (int d0 = 0; d0 < 32; d0 += 4) {
            float4 x1 = *(const float4*)(crow + d0);
            float4 x2 = *(const float4*)(crow + d0 + 32);
            float4 b1 = *(const float4*)(brow + d0);
            float4 b2 = *(const float4*)(brow + d0 + 32);
            float4 cc = *(const float4*)(rt + d0);
            float4 ss = *(const float4*)(rt + 32 + d0);
            x1.x += b1.x; x1.y += b1.y; x1.z += b1.z; x1.w += b1.w;
            x2.x += b2.x; x2.y += b2.y; x2.z += b2.z; x2.w += b2.w;
            float o1x = (x1.x * cc.x - x2.x * ss.x) * scale;
            float o1y = (x1.y * cc.y - x2.y * ss.y) * scale;
            float o1z = (x1.z * cc.z - x2.z * ss.z) * scale;
            float o1w = (x1.w * cc.w - x2.w * ss.w) * scale;
            float o2x = (x2.x * cc.x + x1.x * ss.x) * scale;
            float o2y = (x2.y * cc.y + x1.y * ss.y) * scale;
            float o2z = (x2.z * cc.z + x1.z * ss.z) * scale;
            float o2w = (x2.w * cc.w + x1.w * ss.w) * scale;
            *(__half2*)(drow + d0)      = __floats2half2_rn(o1x, o1y);
            *(__half2*)(drow + d0 + 2)  = __floats2half2_rn(o1z, o1w);
            *(__half2*)(drow + d0 + 32) = __floats2half2_rn(o2x, o2y);
            *(__half2*)(drow + d0 + 34) = __floats2half2_rn(o2z, o2w);
        }
    } else {
#pragma unroll
        for (int d0 = 0; d0 < 64; d0 += 4) {
            float4 x = *(const float4*)(crow + d0);
            float4 bb = *(const float4*)(brow + d0);
            *(__half2*)(drow + d0)     = __floats2half2_rn(x.x + bb.x, x.y + bb.y);
            *(__half2*)(drow + d0 + 2) = __floats2half2_rn(x.z + bb.z, x.w + bb.w);
        }
    }
}

// ---------------------------------------------------------------------------
// Output projection + bias, 128x64 tiles for SM fill. grid (16, 32).
// 8 warps: wm=wid&3 (32 rows), wn=wid>>2 in {0,1} (32 cols). acc 2x2.
// ---------------------------------------------------------------------------
#define OSTGH ((128+64)*LDAH)     // halves per stage = 13824
#define OLDC  68

__device__ __forceinline__ void out_issue(const __half* __restrict__ A,
                                          const __half* __restrict__ W,
                                          __half* sm, int kb, int s, int tid)
{
    __half* As = sm + s * OSTGH;               // 128 rows A, then 64 rows W
    __half* Ws = As + 128 * LDAH;
#pragma unroll
    for (int i = 0; i < 6; i++) {
        int idx = tid + i * 256;               // 0..1535
        int r = idx >> 3, c = (idx & 7) * 8;   // r 0..191
        if (r < 128)
            cp16(sm_u32(As + r * LDAH + c), A + (size_t)r * HIDDEN + kb * 64 + c);
        else
            cp16(sm_u32(Ws + (r - 128) * LDAH + c),
                 W + (size_t)(r - 128) * HIDDEN + kb * 64 + c);
    }
    cp_commit();
}

__global__ void __launch_bounds__(256, 2)
out_mma(const float* __restrict__ bo, float* __restrict__ out)
{
    extern __shared__ char smraw[];
    __half* sm = (__half*)smraw;
    const int tid = threadIdx.x, wid = tid >> 5;
    const int wm = wid & 3, wn = wid >> 2;     // wn in 0..1
    const int m0 = blockIdx.y * 128, n0 = blockIdx.x * 64;

    const __half* A = g_ao + (size_t)m0 * HIDDEN;
    const __half* W = g_wh + 3 * (size_t)HH + (size_t)n0 * HIDDEN;

    HFragC acc[2][2];
#pragma unroll
    for (int mi = 0; mi < 2; mi++)
#pragma unroll
        for (int ni = 0; ni < 2; ni++)
            wmma::fill_fragment(acc[mi][ni], 0.0f);

    out_issue(A, W, sm, 0, 0, tid);
    out_issue(A, W, sm, 1, 1, tid);

    for (int kb = 0; kb < 16; kb++) {
        int s = kb % 3;
        if (kb < 15) cp_wait1(); else cp_wait0();
        __syncthreads();
        if (kb + 2 < 16) out_issue(A, W, sm, kb + 2, (kb + 2) % 3, tid);

        __half* As = sm + s * OSTGH;
        __half* Ws = As + 128 * LDAH;
#pragma unroll
        for (int kk = 0; kk < 64; kk += 16) {
            HFragA af[2];
            HFragB bf[2];
#pragma unroll
            for (int mi = 0; mi < 2; mi++)
                wmma::load_matrix_sync(af[mi], &As[(wm * 32 + mi * 16) * LDAH + kk], LDAH);
#pragma unroll
            for (int ni = 0; ni < 2; ni++)
                wmma::load_matrix_sync(bf[ni], &Ws[(wn * 32 + ni * 16) * LDAH + kk], LDAH);
#pragma unroll
            for (int mi = 0; mi < 2; mi++)
#pragma unroll
                for (int ni = 0; ni < 2; ni++)
                    wmma::mma_sync(acc[mi][ni], af[mi], bf[ni], acc[mi][ni]);
        }
    }
    __syncthreads();

    float* Cs = (float*)smraw;                 // 128 x OLDC fp32 = 34816 B
#pragma unroll
    for (int mi = 0; mi < 2; mi++)
#pragma unroll
        for (int ni = 0; ni < 2; ni++)
            wmma::store_matrix_sync(Cs + (wm * 32 + mi * 16) * OLDC + wn * 32 + ni * 16,
                                    acc[mi][ni], OLDC, wmma::mem_row_major);
    __syncthreads();

    const int r = tid >> 1, hf = tid & 1;
    const float* crow = Cs + r * OLDC + hf * 32;
    const float* brow = bo + n0 + hf * 32;
    float* orow = out + (size_t)(m0 + r) * HIDDEN + n0 + hf * 32;
#pragma unroll
    for (int j = 0; j < 32; j += 4) {
        float4 x = *(const float4*)(crow + j);
        float4 bb = *(const float4*)(brow + j);
        x.x += bb.x; x.y += bb.y; x.z += bb.z; x.w += bb.w;
        *(float4*)(orow + j) = x;
    }
}

// ---------------------------------------------------------------------------
// Flash attention fp16: mma.m16n8k16, ldmatrix.x4, register-resident P.
// Softmax: ex2.f16x2 + row-sums via ones-MMA (unconditional rescale).
// grid (SEQ/128, BHN), 256 threads / 8 warps; warp owns q-rows [wid*16,+16).
// ---------------------------------------------------------------------------
#define FPH 72                    // halves; 144B row stride
#define KROWS 128                 // keys per stage
#define KVH (KROWS*FPH)           // halves per K (or V) stage
#define ONES_H2 0x3C003C00u       // (1.0h, 1.0h)

__global__ void __launch_bounds__(256, 2)
flash_mma()
{
    extern __shared__ char smraw[];
    __half* KsB = (__half*)smraw;            // 2 stages [128][FPH]
    __half* VsB = KsB + 2 * KVH;             // 2 stages [128][FPH]

    const int tid = threadIdx.x, wid = tid >> 5, lane = tid & 31;
    const int g = lane >> 2, t = lane & 3;
    const int bh = blockIdx.y;
    const int q0 = blockIdx.x * 128;
    const int r0 = wid * 16;

    const int k4off = ((lane >> 4) * 8 + (lane & 7)) * FPH + ((lane >> 3) & 1) * 8;
    const int v4off = (((lane >> 3) & 1) * 8 + (lane & 7)) * FPH + (lane >> 4) * 8;

    const __half* q0p = g_q + ((size_t)(bh * SEQ + q0 + r0 + g)) * HEAD_DIM;
    const __half* q8p = q0p + 8 * HEAD_DIM;
    uint32_t qa[4][4];
#pragma unroll
    for (int kb = 0; kb < 4; kb++) {
        qa[kb][0] = *(const uint32_t*)(q0p + kb * 16 + 2 * t);
        qa[kb][1] = *(const uint32_t*)(q8p + kb * 16 + 2 * t);
        qa[kb][2] = *(const uint32_t*)(q0p + kb * 16 + 8 + 2 * t);
        qa[kb][3] = *(const uint32_t*)(q8p + kb * 16 + 8 + 2 * t);
    }

    float oacc[8][4];
#pragma unroll
    for (int nb = 0; nb < 8; nb++)
#pragma unroll
        for (int e = 0; e < 4; e++) oacc[nb][e] = 0.f;
    float mA = -1e30f, mB = -1e30f, lA = 0.f, lB = 0.f;

    const __half* kbase = g_k + (size_t)bh * SEQ * HEAD_DIM;
    const __half* vbase = g_v + (size_t)bh * SEQ * HEAD_DIM;
    auto issue = [&](int kt, int s) {
        __half* Kd = KsB + s * KVH;
        __half* Vd = VsB + s * KVH;
        const __half* ks = kbase + (size_t)kt * KROWS * HEAD_DIM;
        const __half* vs = vbase + (size_t)kt * KROWS * HEAD_DIM;
#pragma unroll
        for (int i = 0; i < 4; i++) {
            int idx = tid + i * 256;            // 0..1023
            int r = idx >> 3, c = (idx & 7) * 8;
            cp16(sm_u32(Kd + r * FPH + c), ks + r * 64 + c);
            cp16(sm_u32(Vd + r * FPH + c), vs + r * 64 + c);
        }
        cp_commit();
    };

    issue(0, 0);

    for (int kt = 0; kt < SEQ / KROWS; kt++) {
        int s = kt & 1;
        cp_wait0();
        __syncthreads();
        if (kt + 1 < SEQ / KROWS) issue(kt + 1, s ^ 1);

#pragma unroll
        for (int hlf = 0; hlf < 2; hlf++) {
            const uint32_t Ku = sm_u32(KsB + s * KVH + hlf * 64 * FPH);
            const uint32_t Vu = sm_u32(VsB + s * KVH + hlf * 64 * FPH);

            // ---- S = Q K^T (log2 domain) ----
            float sacc[8][4];
#pragma unroll
            for (int nb = 0; nb < 8; nb++)
#pragma unroll
                for (int e = 0; e < 4; e++) sacc[nb][e] = 0.f;

#pragma unroll
            for (int nb2 = 0; nb2 < 4; nb2++) {
#pragma unroll
                for (int kb = 0; kb < 4; kb++) {
                    uint32_t b0, b1, b2, b3;
                    ldsm_x4(b0, b1, b2, b3,
                            Ku + (uint32_t)(nb2 * 16 * FPH + kb * 16 + k4off) * 2);
                    mma16(sacc[2 * nb2],     qa[kb], b0, b1);
                    mma16(sacc[2 * nb2 + 1], qa[kb], b2, b3);
                }
            }

            // ---- row max ----
            float rmA = -1e30f, rmB = -1e30f;
#pragma unroll
            for (int nb = 0; nb < 8; nb++) {
                rmA = fmaxf(rmA, fmaxf(sacc[nb][0], sacc[nb][1]));
                rmB = fmaxf(rmB, fmaxf(sacc[nb][2], sacc[nb][3]));
            }
            rmA = fmaxf(rmA, __shfl_xor_sync(0xffffffffu, rmA, 1));
            rmA = fmaxf(rmA, __shfl_xor_sync(0xffffffffu, rmA, 2));
            rmB = fmaxf(rmB, __shfl_xor_sync(0xffffffffu, rmB, 1));
            rmB = fmaxf(rmB, __shfl_xor_sync(0xffffffffu, rmB, 2));

            float mnA = fmaxf(mA, rmA), mnB = fmaxf(mB, rmB);
            float aA = ex2(mA - mnA), aB = ex2(mB - mnB);

            // ---- P = 2^(S-m) fp16 pairs; directly PV A-frags ----
            uint32_t pall[16];
#pragma unroll
            for (int nb = 0; nb < 8; nb++) {
                pall[2 * nb]     = ex2_h2(pack_h2(sacc[nb][0] - mnA, sacc[nb][1] - mnA));
                pall[2 * nb + 1] = ex2_h2(pack_h2(sacc[nb][2] - mnB, sacc[nb][3] - mnB));
            }

            // ---- row sums via ones-MMA ----
            float rsum[4] = {0.f, 0.f, 0.f, 0.f};
#pragma unroll
            for (int kb2 = 0; kb2 < 4; kb2++)
                mma16(rsum, &pall[4 * kb2], ONES_H2, ONES_H2);

            lA = lA * aA + rsum[0];  mA = mnA;
            lB = lB * aB + rsum[2];  mB = mnB;
#pragma unroll
            for (int nb = 0; nb < 8; nb++) {
                oacc[nb][0] *= aA; oacc[nb][1] *= aA;
                oacc[nb][2] *= aB; oacc[nb][3] *= aB;
            }

            // ---- O += P V ----
#pragma unroll
            for (int kb2 = 0; kb2 < 4; kb2++) {
#pragma unroll
                for (int nb2 = 0; nb2 < 4; nb2++) {
                    uint32_t b0, b1, b2, b3;
                    ldsm_x4_t(b0, b1, b2, b3,
                              Vu + (uint32_t)(kb2 * 16 * FPH + v4off + nb2 * 16) * 2);
                    mma16(oacc[2 * nb2],     &pall[4 * kb2], b0, b1);
                    mma16(oacc[2 * nb2 + 1], &pall[4 * kb2], b2, b3);
                }
            }
        }
    }

    const int b = bh >> 4, h = bh & 15;
    float invA = 1.0f / lA, invB = 1.0f / lB;
    int rA = q0 + r0 + g, rB = rA + 8;
#pragma unroll
    for (int nb = 0; nb < 8; nb++) {
        int col = h * HEAD_DIM + nb * 8 + 2 * t;
        *(__half2*)&g_ao[((size_t)(b * SEQ + rA)) * HIDDEN + col] =
            __floats2half2_rn(oacc[nb][0] * invA, oacc[nb][1] * invA);
        *(__half2*)&g_ao[((size_t)(b * SEQ + rB)) * HIDDEN + col] =
            __floats2half2_rn(oacc[nb][2] * invB, oacc[nb][3] * invB);
    }
}

// ---------------------------------------------------------------------------
extern "C" void kernel_launch(void* const* d_in, const int* in_sizes, int n_in,
                              void* d_out, int out_size)
{
    const float* X  = (const float*)d_in[0];
    const float* Wq = (const float*)d_in[1];
    const float* bq = (const float*)d_in[2];
    const float* Wk = (const float*)d_in[3];
    const float* bk = (const float*)d_in[4];
    const float* Wv = (const float*)d_in[5];
    const float* bv = (const float*)d_in[6];
    const float* Wo = (const float*)d_in[7];
    const float* bo = (const float*)d_in[8];
    float* out = (float*)d_out;

    static const int GEMM_SMEM  = 3 * STGH * 2;       // 110592
    static const int OUT_SMEM   = 3 * OSTGH * 2;      // 82944 (covers Cs 34816)
    static const int FLASH_SMEM = 4 * KVH * 2;        // 73728
    cudaFuncSetAttribute(qkv_mma,  cudaFuncAttributeMaxDynamicSharedMemorySize, GEMM_SMEM);
    cudaFuncSetAttribute(out_mma,  cudaFuncAttributeMaxDynamicSharedMemorySize, OUT_SMEM);
    cudaFuncSetAttribute(flash_mma, cudaFuncAttributeMaxDynamicSharedMemorySize, FLASH_SMEM);

    conv_kernel<<<(CONVN + SEQ * 32) / 256, 256>>>(X, Wq, Wk, Wv, Wo);

    dim3 gq(HIDDEN / 128, MTOT / 128, 3);
    qkv_mma<<<gq, 256, GEMM_SMEM>>>(bq, bk, bv);

    dim3 gf(SEQ / 128, BHN);
    flash_mma<<<gf, 256, FLASH_SMEM>>>();

    dim3 go(HIDDEN / 64, MTOT / 128, 1);
    out_mma<<<go, 256, OUT_SMEM>>>(bo, out);
}

// round 16
// speedup vs baseline: 1.0278x; 1.0278x over previous
#include <cuda_runtime.h>
#include <cuda_fp16.h>
#include <mma.h>
#include <math.h>
#include <cstdint>

using namespace nvcuda;

#define BATCH    2
#define SEQ      2048
#define HIDDEN   1024
#define HEADS    16
#define HEAD_DIM 64
#define MTOT     (BATCH*SEQ)      // 4096
#define BHN      (BATCH*HEADS)    // 32
#define HH       (HIDDEN*HIDDEN)

// scratch (allocation-free rule: __device__ globals)
static __device__ __half g_xh[MTOT*HIDDEN];        // X in fp16
static __device__ __half g_wh[4*HH];               // Wq,Wk,Wv,Wo in fp16
static __device__ float  g_rt[SEQ*64];             // rope: [s][0:32)=cos,[32:64)=sin
static __device__ __half g_q [BHN*SEQ*HEAD_DIM];   // [B,H,S,D] fp16 (q scaled by 1/8*log2e)
static __device__ __half g_k [BHN*SEQ*HEAD_DIM];
static __device__ __half g_v [BHN*SEQ*HEAD_DIM];
static __device__ __half g_ao[MTOT*HIDDEN];        // attention out fp16

// ---------------------------------------------------------------------------
// helpers
// ---------------------------------------------------------------------------
__device__ __forceinline__ void cp16(uint32_t dst, const void* src) {
    asm volatile("cp.async.cg.shared.global [%0], [%1], 16;" :: "r"(dst), "l"(src));
}
__device__ __forceinline__ void cp_commit() {
    asm volatile("cp.async.commit_group;" ::: "memory");
}
__device__ __forceinline__ void cp_wait0() {
    asm volatile("cp.async.wait_group 0;" ::: "memory");
}
__device__ __forceinline__ void cp_wait1() {
    asm volatile("cp.async.wait_group 1;" ::: "memory");
}
__device__ __forceinline__ void cp_wait2() {
    asm volatile("cp.async.wait_group 2;" ::: "memory");
}
__device__ __forceinline__ uint32_t sm_u32(const void* p) {
    return (uint32_t)__cvta_generic_to_shared(p);
}
__device__ __forceinline__ uint32_t pack_h2(float lo, float hi) {
    __half2 h = __floats2half2_rn(lo, hi);
    return *reinterpret_cast<uint32_t*>(&h);
}
__device__ __forceinline__ float ex2(float x) {
    float y;
    asm("ex2.approx.ftz.f32 %0, %1;" : "=f"(y) : "f"(x));
    return y;
}
__device__ __forceinline__ uint32_t ex2_h2(uint32_t x) {
    uint32_t y;
    asm("ex2.approx.f16x2 %0, %1;" : "=r"(y) : "r"(x));
    return y;
}
__device__ __forceinline__ void mma16(float d[4], const uint32_t a[4],
                                      uint32_t b0, uint32_t b1)
{
    asm volatile(
        "mma.sync.aligned.m16n8k16.row.col.f32.f16.f16.f32 "
        "{%0,%1,%2,%3}, {%4,%5,%6,%7}, {%8,%9}, {%0,%1,%2,%3};"
        : "+f"(d[0]), "+f"(d[1]), "+f"(d[2]), "+f"(d[3])
        : "r"(a[0]), "r"(a[1]), "r"(a[2]), "r"(a[3]), "r"(b0), "r"(b1));
}
__device__ __forceinline__ void ldsm_x4(uint32_t& r0, uint32_t& r1,
                                        uint32_t& r2, uint32_t& r3, uint32_t addr) {
    asm volatile("ldmatrix.sync.aligned.m8n8.x4.shared.b16 {%0,%1,%2,%3}, [%4];"
                 : "=r"(r0), "=r"(r1), "=r"(r2), "=r"(r3) : "r"(addr));
}
__device__ __forceinline__ void ldsm_x4_t(uint32_t& r0, uint32_t& r1,
                                          uint32_t& r2, uint32_t& r3, uint32_t addr) {
    asm volatile("ldmatrix.sync.aligned.m8n8.x4.trans.shared.b16 {%0,%1,%2,%3}, [%4];"
                 : "=r"(r0), "=r"(r1), "=r"(r2), "=r"(r3) : "r"(addr));
}

// ---------------------------------------------------------------------------
// setup: fp16 conversion (8 floats/thread, one 16B store) + rope table
// ---------------------------------------------------------------------------
#define XN8 (MTOT*HIDDEN/8)       // 524288
#define WN8 (HH/8)                // 131072 = 2^17
#define CONVN8 (XN8 + 4*WN8)      // 1048576
__global__ void conv_kernel(const float* __restrict__ X,
                            const float* __restrict__ Wq,
                            const float* __restrict__ Wk,
                            const float* __restrict__ Wv,
                            const float* __restrict__ Wo)
{
    int gid = blockIdx.x * blockDim.x + threadIdx.x;
    if (gid < CONVN8) {
        const float4* s4; uint4* d4;
        if (gid < XN8) {
            s4 = (const float4*)X + (size_t)gid * 2;
            d4 = (uint4*)g_xh + gid;
        } else {
            int w = gid - XN8;
            int sel = w >> 17;          // WN8 = 2^17
            int off = w & (WN8 - 1);
            const float* W = (sel == 0) ? Wq : (sel == 1) ? Wk : (sel == 2) ? Wv : Wo;
            s4 = (const float4*)W + (size_t)off * 2;
            d4 = (uint4*)g_wh + (size_t)sel * WN8 + off;
        }
        float4 a = s4[0];
        float4 b = s4[1];
        uint4 o;
        o.x = pack_h2(a.x, a.y);
        o.y = pack_h2(a.z, a.w);
        o.z = pack_h2(b.x, b.y);
        o.w = pack_h2(b.z, b.w);
        *d4 = o;
    } else {
        int t = gid - CONVN8;           // < SEQ*32
        int i = t & 31, s = t >> 5;
        float inv = powf(10000.0f, -(float)i * (1.0f / 32.0f));
        float c, sn;
        sincosf((float)s * inv, &sn, &c);
        g_rt[s * 64 + i]      = c;
        g_rt[s * 64 + 32 + i] = sn;
    }
}

// ---------------------------------------------------------------------------
// fp16 wmma GEMM: C(128x128) = A(128xK)*W(128xK)^T, K=1024, BK=32 halves.
// 4-stage cp.async pipeline, ONE __syncthreads per iteration.
// 8 warps: wm=wid&3 (32 rows), wn=wid>>2 (64 cols).
// ---------------------------------------------------------------------------
#define LDAH 40                   // halves; 80B row stride
#define STGH (2*128*LDAH)         // halves per stage (A+W) = 10240
#define LDC  132

using HFragA = wmma::fragment<wmma::matrix_a, 16, 16, 16, __half, wmma::row_major>;
using HFragB = wmma::fragment<wmma::matrix_b, 16, 16, 16, __half, wmma::col_major>;
using HFragC = wmma::fragment<wmma::accumulator, 16, 16, 16, float>;

__device__ __forceinline__ void hgemm_issue(const __half* __restrict__ A,
                                            const __half* __restrict__ W,
                                            __half* sm, int kb, int s, int tid)
{
    __half* As = sm + s * STGH;
    __half* Ws = As + 128 * LDAH;
#pragma unroll
    for (int i = 0; i < 2; i++) {
        int idx = tid + i * 256;            // 0..511
        int r = idx >> 2, c = (idx & 3) * 8;
        cp16(sm_u32(As + r * LDAH + c), A + (size_t)r * HIDDEN + kb * 32 + c);
        cp16(sm_u32(Ws + r * LDAH + c), W + (size_t)r * HIDDEN + kb * 32 + c);
    }
    cp_commit();
}

__device__ __forceinline__ void hgemm_mainloop(const __half* __restrict__ A,
                                               const __half* __restrict__ W,
                                               __half* sm, HFragC acc[2][4],
                                               int wm, int wn)
{
    const int tid = threadIdx.x;
#pragma unroll
    for (int mi = 0; mi < 2; mi++)
#pragma unroll
        for (int ni = 0; ni < 4; ni++)
            wmma::fill_fragment(acc[mi][ni], 0.0f);

    hgemm_issue(A, W, sm, 0, 0, tid);
    hgemm_issue(A, W, sm, 1, 1, tid);
    hgemm_issue(A, W, sm, 2, 2, tid);

    for (int kb = 0; kb < 32; kb++) {
        int s = kb & 3;
        if      (kb < 30)  cp_wait2();
        else if (kb == 30) cp_wait1();
        else               cp_wait0();
        __syncthreads();
        // stage (kb+3)&3 = (kb-1)&3 was consumed at iter kb-1; all warps are
        // past it once they cross the sync above.
        if (kb + 3 < 32) hgemm_issue(A, W, sm, kb + 3, (kb + 3) & 3, tid);

        __half* As = sm + s * STGH;
        __half* Ws = As + 128 * LDAH;
#pragma unroll
        for (int kk = 0; kk < 32; kk += 16) {
            HFragA af[2];
            HFragB bf[4];
#pragma unroll
            for (int mi = 0; mi < 2; mi++)
                wmma::load_matrix_sync(af[mi], &As[(wm * 32 + mi * 16) * LDAH + kk], LDAH);
#pragma unroll
            for (int ni = 0; ni < 4; ni++)
                wmma::load_matrix_sync(bf[ni], &Ws[(wn * 64 + ni * 16) * LDAH + kk], LDAH);
#pragma unroll
            for (int mi = 0; mi < 2; mi++)
#pragma unroll
                for (int ni = 0; ni < 4; ni++)
                    wmma::mma_sync(acc[mi][ni], af[mi], bf[ni], acc[mi][ni]);
        }
    }
    __syncthreads();   // before epilogue reuses smem
}

__device__ __forceinline__ void stage_C(float* Cs, HFragC acc[2][4], int wm, int wn)
{
#pragma unroll
    for (int mi = 0; mi < 2; mi++)
#pragma unroll
        for (int ni = 0; ni < 4; ni++)
            wmma::store_matrix_sync(Cs + (wm * 32 + mi * 16) * LDC + wn * 64 + ni * 16,
                                    acc[mi][ni], LDC, wmma::mem_row_major);
}

// ---------------------------------------------------------------------------
// QKV projection + bias + RoPE fused epilogue -> fp16. grid (8, 32, 3).
// ---------------------------------------------------------------------------
__global__ void __launch_bounds__(256, 2)
qkv_mma(const float* __restrict__ bq,
        const float* __restrict__ bk,
        const float* __restrict__ bv)
{
    extern __shared__ char smraw[];
    const int tid = threadIdx.x, wid = tid >> 5;
    const int wm = wid & 3, wn = wid >> 2;
    const int m0 = blockIdx.y * 128, n0 = blockIdx.x * 128;
    const int z = blockIdx.z;

    const __half* W = g_wh + (size_t)z * HH;
    const float* bias = (z == 0) ? bq : (z == 1) ? bk : bv;
    __half* dst = (z == 0) ? g_q : (z == 1) ? g_k : g_v;

    HFragC acc[2][4];
    hgemm_mainloop(g_xh + (size_t)m0 * HIDDEN, W + (size_t)n0 * HIDDEN,
                   (__half*)smraw, acc, wm, wn);

    float* Cs = (float*)smraw;
    stage_C(Cs, acc, wm, wn);
    __syncthreads();

    const int r = tid >> 1, hh = tid & 1;
    const int m = m0 + r;
    const int b = m >> 11, s = m & (SEQ - 1);
    const int h = (n0 >> 6) + hh;
    const float* crow = Cs + r * LDC + hh * 64;
    const float* brow = bias + n0 + hh * 64;
    __half* drow = dst + (((size_t)(b * HEADS + h)) * SEQ + s) * HEAD_DIM;

    if (z < 2) {
        const float* rt = g_rt + s * 64;
        const float scale = (z == 0) ? 0.125f * 1.44269504088896f : 1.0f;
#pragma unroll
        for (int d0 = 0; d0 < 32; d0 += 4) {
            float4 x1 = *(const float4*)(crow + d0);
            float4 x2 = *(const float4*)(crow + d0 + 32);
            float4 b1 = *(const float4*)(brow + d0);
            float4 b2 = *(const float4*)(brow + d0 + 32);
            float4 cc = *(const float4*)(rt + d0);
            float4 ss = *(const float4*)(rt + 32 + d0);
            x1.x += b1.x; x1.y += b1.y; x1.z += b1.z; x1.w += b1.w;
            x2.x += b2.x; x2.y += b2.y; x2.z += b2.z; x2.w += b2.w;
            float o1x = (x1.x * cc.x - x2.x * ss.x) * scale;
            float o1y = (x1.y * cc.y - x2.y * ss.y) * scale;
            float o1z = (x1.z * cc.z - x2.z * ss.z) * scale;
            float o1w = (x1.w * cc.w - x2.w * ss.w) * scale;
            float o2x = (x2.x * cc.x + x1.x * ss.x) * scale;
            float o2y = (x2.y * cc.y + x1.y * ss.y) * scale;
            float o2z = (x2.z * cc.z + x1.z * ss.z) * scale;
            float o2w = (x2.w * cc.w + x1.w * ss.w) * scale;
            *(__half2*)(drow + d0)      = __floats2half2_rn(o1x, o1y);
            *(__half2*)(drow + d0 + 2)  = __floats2half2_rn(o1z, o1w);
            *(__half2*)(drow + d0 + 32) = __floats2half2_rn(o2x, o2y);
            *(__half2*)(drow + d0 + 34) = __floats2half2_rn(o2z, o2w);
        }
    } else {
#pragma unroll
        for (int d0 = 0; d0 < 64; d0 += 4) {
            float4 x = *(const float4*)(crow + d0);
            float4 bb = *(const float4*)(brow + d0);
            *(__half2*)(drow + d0)     = __floats2half2_rn(x.x + bb.x, x.y + bb.y);
            *(__half2*)(drow + d0 + 2) = __floats2half2_rn(x.z + bb.z, x.w + bb.w);
        }
    }
}

// ---------------------------------------------------------------------------
// Output projection + bias, 128x128 tiles. grid (8, 32).
// ---------------------------------------------------------------------------
__global__ void __launch_bounds__(256, 2)
out_mma(const float* __restrict__ bo, float* __restrict__ out)
{
    extern __shared__ char smraw[];
    const int tid = threadIdx.x, wid = tid >> 5;
    const int wm = wid & 3, wn = wid >> 2;
    const int m0 = blockIdx.y * 128, n0 = blockIdx.x * 128;

    HFragC acc[2][4];
    hgemm_mainloop(g_ao + (size_t)m0 * HIDDEN,
                   g_wh + 3 * (size_t)HH + (size_t)n0 * HIDDEN,
                   (__half*)smraw, acc, wm, wn);

    float* Cs = (float*)smraw;
    stage_C(Cs, acc, wm, wn);
    __syncthreads();

    const int r = tid >> 1, half = tid & 1;
    const float* crow = Cs + r * LDC + half * 64;
    const float* brow = bo + n0 + half * 64;
    float* orow = out + (size_t)(m0 + r) * HIDDEN + n0 + half * 64;
#pragma unroll
    for (int j = 0; j < 64; j += 4) {
        float4 x = *(const float4*)(crow + j);
        float4 bb = *(const float4*)(brow + j);
        x.x += bb.x; x.y += bb.y; x.z += bb.z; x.w += bb.w;
        *(float4*)(orow + j) = x;
    }
}

// ---------------------------------------------------------------------------
// Flash attention fp16: mma.m16n8k16, ldmatrix.x4, register-resident P.
// Softmax: ex2.f16x2 + row-sums via ones-MMA (unconditional rescale).
// grid (SEQ/128, BHN), 256 threads / 8 warps; warp owns q-rows [wid*16,+16).
// K/V staged 128 keys at a time (double-buffered), two 64-key halves each.
// ---------------------------------------------------------------------------
#define FPH 72                    // halves; 144B row stride
#define KROWS 128                 // keys per stage
#define KVH (KROWS*FPH)           // halves per K (or V) stage
#define ONES_H2 0x3C003C00u       // (1.0h, 1.0h)

__global__ void __launch_bounds__(256, 2)
flash_mma()
{
    extern __shared__ char smraw[];
    __half* KsB = (__half*)smraw;            // 2 stages [128][FPH]
    __half* VsB = KsB + 2 * KVH;             // 2 stages [128][FPH]

    const int tid = threadIdx.x, wid = tid >> 5, lane = tid & 31;
    const int g = lane >> 2, t = lane & 3;
    const int bh = blockIdx.y;
    const int q0 = blockIdx.x * 128;
    const int r0 = wid * 16;

    const int k4off = ((lane >> 4) * 8 + (lane & 7)) * FPH + ((lane >> 3) & 1) * 8;
    const int v4off = (((lane >> 3) & 1) * 8 + (lane & 7)) * FPH + (lane >> 4) * 8;

    const __half* q0p = g_q + ((size_t)(bh * SEQ + q0 + r0 + g)) * HEAD_DIM;
    const __half* q8p = q0p + 8 * HEAD_DIM;
    uint32_t qa[4][4];
#pragma unroll
    for (int kb = 0; kb < 4; kb++) {
        qa[kb][0] = *(const uint32_t*)(q0p + kb * 16 + 2 * t);
        qa[kb][1] = *(const uint32_t*)(q8p + kb * 16 + 2 * t);
        qa[kb][2] = *(const uint32_t*)(q0p + kb * 16 + 8 + 2 * t);
        qa[kb][3] = *(const uint32_t*)(q8p + kb * 16 + 8 + 2 * t);
    }

    float oacc[8][4];
#pragma unroll
    for (int nb = 0; nb < 8; nb++)
#pragma unroll
        for (int e = 0; e < 4; e++) oacc[nb][e] = 0.f;
    float mA = -1e30f, mB = -1e30f, lA = 0.f, lB = 0.f;

    const __half* kbase = g_k + (size_t)bh * SEQ * HEAD_DIM;
    const __half* vbase = g_v + (size_t)bh * SEQ * HEAD_DIM;
    auto issue = [&](int kt, int s) {
        __half* Kd = KsB + s * KVH;
        __half* Vd = VsB + s * KVH;
        const __half* ks = kbase + (size_t)kt * KROWS * HEAD_DIM;
        const __half* vs = vbase + (size_t)kt * KROWS * HEAD_DIM;
#pragma unroll
        for (int i = 0; i < 4; i++) {
            int idx = tid + i * 256;            // 0..1023
            int r = idx >> 3, c = (idx & 7) * 8;
            cp16(sm_u32(Kd + r * FPH + c), ks + r * 64 + c);
            cp16(sm_u32(Vd + r * FPH + c), vs + r * 64 + c);
        }
        cp_commit();
    };

    issue(0, 0);

    for (int kt = 0; kt < SEQ / KROWS; kt++) {
        int s = kt & 1;
        cp_wait0();
        __syncthreads();
        if (kt + 1 < SEQ / KROWS) issue(kt + 1, s ^ 1);

#pragma unroll
        for (int hlf = 0; hlf < 2; hlf++) {
            const uint32_t Ku = sm_u32(KsB + s * KVH + hlf * 64 * FPH);
            const uint32_t Vu = sm_u32(VsB + s * KVH + hlf * 64 * FPH);

            // ---- S = Q K^T (log2 domain) ----
            float sacc[8][4];
#pragma unroll
            for (int nb = 0; nb < 8; nb++)
#pragma unroll
                for (int e = 0; e < 4; e++) sacc[nb][e] = 0.f;

#pragma unroll
            for (int nb2 = 0; nb2 < 4; nb2++) {
#pragma unroll
                for (int kb = 0; kb < 4; kb++) {
                    uint32_t b0, b1, b2, b3;
                    ldsm_x4(b0, b1, b2, b3,
                            Ku + (uint32_t)(nb2 * 16 * FPH + kb * 16 + k4off) * 2);
                    mma16(sacc[2 * nb2],     qa[kb], b0, b1);
                    mma16(sacc[2 * nb2 + 1], qa[kb], b2, b3);
                }
            }

            // ---- row max ----
            float rmA = -1e30f, rmB = -1e30f;
#pragma unroll
            for (int nb = 0; nb < 8; nb++) {
                rmA = fmaxf(rmA, fmaxf(sacc[nb][0], sacc[nb][1]));
                rmB = fmaxf(rmB, fmaxf(sacc[nb][2], sacc[nb][3]));
            }
            rmA = fmaxf(rmA, __shfl_xor_sync(0xffffffffu, rmA, 1));
            rmA = fmaxf(rmA, __shfl_xor_sync(0xffffffffu, rmA, 2));
            rmB = fmaxf(rmB, __shfl_xor_sync(0xffffffffu, rmB, 1));
            rmB = fmaxf(rmB, __shfl_xor_sync(0xffffffffu, rmB, 2));

            float mnA = fmaxf(mA, rmA), mnB = fmaxf(mB, rmB);
            float aA = ex2(mA - mnA), aB = ex2(mB - mnB);

            // ---- P = 2^(S-m) fp16 pairs (ex2.f16x2); directly PV A-frags ----
            uint32_t pall[16];
#pragma unroll
            for (int nb = 0; nb < 8; nb++) {
                pall[2 * nb]     = ex2_h2(pack_h2(sacc[nb][0] - mnA, sacc[nb][1] - mnA));
                pall[2 * nb + 1] = ex2_h2(pack_h2(sacc[nb][2] - mnB, sacc[nb][3] - mnB));
            }

            // ---- row sums via ones-MMA (every lane gets the row sum) ----
            float rsum[4] = {0.f, 0.f, 0.f, 0.f};
#pragma unroll
            for (int kb2 = 0; kb2 < 4; kb2++)
                mma16(rsum, &pall[4 * kb2], ONES_H2, ONES_H2);

            lA = lA * aA + rsum[0];  mA = mnA;
            lB = lB * aB + rsum[2];  mB = mnB;
#pragma unroll
            for (int nb = 0; nb < 8; nb++) {
                oacc[nb][0] *= aA; oacc[nb][1] *= aA;
                oacc[nb][2] *= aB; oacc[nb][3] *= aB;
            }

            // ---- O += P V ----
#pragma unroll
            for (int kb2 = 0; kb2 < 4; kb2++) {
#pragma unroll
                for (int nb2 = 0; nb2 < 4; nb2++) {
                    uint32_t b0, b1, b2, b3;
                    ldsm_x4_t(b0, b1, b2, b3,
                              Vu + (uint32_t)(kb2 * 16 * FPH + v4off + nb2 * 16) * 2);
                    mma16(oacc[2 * nb2],     &pall[4 * kb2], b0, b1);
                    mma16(oacc[2 * nb2 + 1], &pall[4 * kb2], b2, b3);
                }
            }
        }
    }

    const int b = bh >> 4, h = bh & 15;
    float invA = 1.0f / lA, invB = 1.0f / lB;
    int rA = q0 + r0 + g, rB = rA + 8;
#pragma unroll
    for (int nb = 0; nb < 8; nb++) {
        int col = h * HEAD_DIM + nb * 8 + 2 * t;
        *(__half2*)&g_ao[((size_t)(b * SEQ + rA)) * HIDDEN + col] =
            __floats2half2_rn(oacc[nb][0] * invA, oacc[nb][1] * invA);
        *(__half2*)&g_ao[((size_t)(b * SEQ + rB)) * HIDDEN + col] =
            __floats2half2_rn(oacc[nb][2] * invB, oacc[nb][3] * invB);
    }
}

// ---------------------------------------------------------------------------
extern "C" void kernel_launch(void* const* d_in, const int* in_sizes, int n_in,
                              void* d_out, int out_size)
{
    const float* X  = (const float*)d_in[0];
    const float* Wq = (const float*)d_in[1];
    const float* bq = (const float*)d_in[2];
    const float* Wk = (const float*)d_in[3];
    const float* bk = (const float*)d_in[4];
    const float* Wv = (const float*)d_in[5];
    const float* bv = (const float*)d_in[6];
    const float* Wo = (const float*)d_in[7];
    const float* bo = (const float*)d_in[8];
    float* out = (float*)d_out;

    static const int GEMM_SMEM  = 4 * STGH * 2;       // 81920 (covers Cs 67584)
    static const int FLASH_SMEM = 4 * KVH * 2;        // 73728
    cudaFuncSetAttribute(qkv_mma,  cudaFuncAttributeMaxDynamicSharedMemorySize, GEMM_SMEM);
    cudaFuncSetAttribute(out_mma,  cudaFuncAttributeMaxDynamicSharedMemorySize, GEMM_SMEM);
    cudaFuncSetAttribute(flash_mma, cudaFuncAttributeMaxDynamicSharedMemorySize, FLASH_SMEM);

    conv_kernel<<<(CONVN8 + SEQ * 32) / 256, 256>>>(X, Wq, Wk, Wv, Wo);

    dim3 gq(HIDDEN / 128, MTOT / 128, 3);
    qkv_mma<<<gq, 256, GEMM_SMEM>>>(bq, bk, bv);

    dim3 gf(SEQ / 128, BHN);
    flash_mma<<<gf, 256, FLASH_SMEM>>>();

    dim3 go(HIDDEN / 128, MTOT / 128, 1);
    out_mma<<<go, 256, GEMM_SMEM>>>(bo, out);
}

// round 17
// speedup vs baseline: 1.0307x; 1.0028x over previous
#include <cuda_runtime.h>
#include <cuda_fp16.h>
#include <mma.h>
#include <math.h>
#include <cstdint>

using namespace nvcuda;

#define BATCH    2
#define SEQ      2048
#define HIDDEN   1024
#define HEADS    16
#define HEAD_DIM 64
#define MTOT     (BATCH*SEQ)      // 4096
#define BHN      (BATCH*HEADS)    // 32
#define HH       (HIDDEN*HIDDEN)

// scratch (allocation-free rule: __device__ globals)
static __device__ __half g_xh[MTOT*HIDDEN];        // X in fp16
static __device__ __half g_wh[4*HH];               // Wq,Wk,Wv,Wo in fp16
static __device__ float  g_rt[SEQ*64];             // rope: [s][0:32)=cos,[32:64)=sin
static __device__ __half g_q [BHN*SEQ*HEAD_DIM];   // [B,H,S,D] fp16 (q scaled by 1/8*log2e)
static __device__ __half g_k [BHN*SEQ*HEAD_DIM];
static __device__ __half g_v [BHN*SEQ*HEAD_DIM];
static __device__ __half g_ao[MTOT*HIDDEN];        // attention out fp16

// ---------------------------------------------------------------------------
// helpers
// ---------------------------------------------------------------------------
__device__ __forceinline__ void gdc_wait() {
    asm volatile("griddepcontrol.wait;" ::: "memory");
}
__device__ __forceinline__ void cp16(uint32_t dst, const void* src) {
    asm volatile("cp.async.cg.shared.global [%0], [%1], 16;" :: "r"(dst), "l"(src));
}
__device__ __forceinline__ void cp_commit() {
    asm volatile("cp.async.commit_group;" ::: "memory");
}
__device__ __forceinline__ void cp_wait0() {
    asm volatile("cp.async.wait_group 0;" ::: "memory");
}
__device__ __forceinline__ void cp_wait1() {
    asm volatile("cp.async.wait_group 1;" ::: "memory");
}
__device__ __forceinline__ void cp_wait2() {
    asm volatile("cp.async.wait_group 2;" ::: "memory");
}
__device__ __forceinline__ uint32_t sm_u32(const void* p) {
    return (uint32_t)__cvta_generic_to_shared(p);
}
__device__ __forceinline__ uint32_t pack_h2(float lo, float hi) {
    __half2 h = __floats2half2_rn(lo, hi);
    return *reinterpret_cast<uint32_t*>(&h);
}
__device__ __forceinline__ float ex2(float x) {
    float y;
    asm("ex2.approx.ftz.f32 %0, %1;" : "=f"(y) : "f"(x));
    return y;
}
__device__ __forceinline__ uint32_t ex2_h2(uint32_t x) {
    uint32_t y;
    asm("ex2.approx.f16x2 %0, %1;" : "=r"(y) : "r"(x));
    return y;
}
__device__ __forceinline__ void mma16(float d[4], const uint32_t a[4],
                                      uint32_t b0, uint32_t b1)
{
    asm volatile(
        "mma.sync.aligned.m16n8k16.row.col.f32.f16.f16.f32 "
        "{%0,%1,%2,%3}, {%4,%5,%6,%7}, {%8,%9}, {%0,%1,%2,%3};"
        : "+f"(d[0]), "+f"(d[1]), "+f"(d[2]), "+f"(d[3])
        : "r"(a[0]), "r"(a[1]), "r"(a[2]), "r"(a[3]), "r"(b0), "r"(b1));
}
__device__ __forceinline__ void ldsm_x4(uint32_t& r0, uint32_t& r1,
                                        uint32_t& r2, uint32_t& r3, uint32_t addr) {
    asm volatile("ldmatrix.sync.aligned.m8n8.x4.shared.b16 {%0,%1,%2,%3}, [%4];"
                 : "=r"(r0), "=r"(r1), "=r"(r2), "=r"(r3) : "r"(addr));
}
__device__ __forceinline__ void ldsm_x4_t(uint32_t& r0, uint32_t& r1,
                                          uint32_t& r2, uint32_t& r3, uint32_t addr) {
    asm volatile("ldmatrix.sync.aligned.m8n8.x4.trans.shared.b16 {%0,%1,%2,%3}, [%4];"
                 : "=r"(r0), "=r"(r1), "=r"(r2), "=r"(r3) : "r"(addr));
}

// ---------------------------------------------------------------------------
// setup: fp16 conversion (8 floats/thread, one 16B store) + rope table
// ---------------------------------------------------------------------------
#define XN8 (MTOT*HIDDEN/8)       // 524288
#define WN8 (HH/8)                // 131072 = 2^17
#define CONVN8 (XN8 + 4*WN8)      // 1048576
__global__ void conv_kernel(const float* __restrict__ X,
                            const float* __restrict__ Wq,
                            const float* __restrict__ Wk,
                            const float* __restrict__ Wv,
                            const float* __restrict__ Wo)
{
    int gid = blockIdx.x * blockDim.x + threadIdx.x;
    if (gid < CONVN8) {
        const float4* s4; uint4* d4;
        if (gid < XN8) {
            s4 = (const float4*)X + (size_t)gid * 2;
            d4 = (uint4*)g_xh + gid;
        } else {
            int w = gid - XN8;
            int sel = w >> 17;          // WN8 = 2^17
            int off = w & (WN8 - 1);
            const float* W = (sel == 0) ? Wq : (sel == 1) ? Wk : (sel == 2) ? Wv : Wo;
            s4 = (const float4*)W + (size_t)off * 2;
            d4 = (uint4*)g_wh + (size_t)sel * WN8 + off;
        }
        float4 a = s4[0];
        float4 b = s4[1];
        uint4 o;
        o.x = pack_h2(a.x, a.y);
        o.y = pack_h2(a.z, a.w);
        o.z = pack_h2(b.x, b.y);
        o.w = pack_h2(b.z, b.w);
        *d4 = o;
    } else {
        int t = gid - CONVN8;           // < SEQ*32
        int i = t & 31, s = t >> 5;
        float inv = powf(10000.0f, -(float)i * (1.0f / 32.0f));
        float c, sn;
        sincosf((float)s * inv, &sn, &c);
        g_rt[s * 64 + i]      = c;
        g_rt[s * 64 + 32 + i] = sn;
    }
}

// ---------------------------------------------------------------------------
// fp16 wmma GEMM: C(128x128) = A(128xK)*W(128xK)^T, K=1024, BK=32 halves.
// 4-stage cp.async pipeline, ONE __syncthreads per iteration.
// 8 warps: wm=wid&3 (32 rows), wn=wid>>2 (64 cols).
// ---------------------------------------------------------------------------
#define LDAH 40                   // halves; 80B row stride
#define STGH (2*128*LDAH)         // halves per stage (A+W) = 10240
#define LDC  132

using HFragA = wmma::fragment<wmma::matrix_a, 16, 16, 16, __half, wmma::row_major>;
using HFragB = wmma::fragment<wmma::matrix_b, 16, 16, 16, __half, wmma::col_major>;
using HFragC = wmma::fragment<wmma::accumulator, 16, 16, 16, float>;

__device__ __forceinline__ void hgemm_issue(const __half* __restrict__ A,
                                            const __half* __restrict__ W,
                                            __half* sm, int kb, int s, int tid)
{
    __half* As = sm + s * STGH;
    __half* Ws = As + 128 * LDAH;
#pragma unroll
    for (int i = 0; i < 2; i++) {
        int idx = tid + i * 256;            // 0..511
        int r = idx >> 2, c = (idx & 3) * 8;
        cp16(sm_u32(As + r * LDAH + c), A + (size_t)r * HIDDEN + kb * 32 + c);
        cp16(sm_u32(Ws + r * LDAH + c), W + (size_t)r * HIDDEN + kb * 32 + c);
    }
    cp_commit();
}

__device__ __forceinline__ void hgemm_mainloop(const __half* __restrict__ A,
                                               const __half* __restrict__ W,
                                               __half* sm, HFragC acc[2][4],
                                               int wm, int wn)
{
    const int tid = threadIdx.x;
#pragma unroll
    for (int mi = 0; mi < 2; mi++)
#pragma unroll
        for (int ni = 0; ni < 4; ni++)
            wmma::fill_fragment(acc[mi][ni], 0.0f);

    hgemm_issue(A, W, sm, 0, 0, tid);
    hgemm_issue(A, W, sm, 1, 1, tid);
    hgemm_issue(A, W, sm, 2, 2, tid);

    for (int kb = 0; kb < 32; kb++) {
        int s = kb & 3;
        if      (kb < 30)  cp_wait2();
        else if (kb == 30) cp_wait1();
        else               cp_wait0();
        __syncthreads();
        // stage (kb+3)&3 = (kb-1)&3 was consumed at iter kb-1; all warps are
        // past it once they cross the sync above.
        if (kb + 3 < 32) hgemm_issue(A, W, sm, kb + 3, (kb + 3) & 3, tid);

        __half* As = sm + s * STGH;
        __half* Ws = As + 128 * LDAH;
#pragma unroll
        for (int kk = 0; kk < 32; kk += 16) {
            HFragA af[2];
            HFragB bf[4];
#pragma unroll
            for (int mi = 0; mi < 2; mi++)
                wmma::load_matrix_sync(af[mi], &As[(wm * 32 + mi * 16) * LDAH + kk], LDAH);
#pragma unroll
            for (int ni = 0; ni < 4; ni++)
                wmma::load_matrix_sync(bf[ni], &Ws[(wn * 64 + ni * 16) * LDAH + kk], LDAH);
#pragma unroll
            for (int mi = 0; mi < 2; mi++)
#pragma unroll
                for (int ni = 0; ni < 4; ni++)
                    wmma::mma_sync(acc[mi][ni], af[mi], bf[ni], acc[mi][ni]);
        }
    }
    __syncthreads();   // before epilogue reuses smem
}

__device__ __forceinline__ void stage_C(float* Cs, HFragC acc[2][4], int wm, int wn)
{
#pragma unroll
    for (int mi = 0; mi < 2; mi++)
#pragma unroll
        for (int ni = 0; ni < 4; ni++)
            wmma::store_matrix_sync(Cs + (wm * 32 + mi * 16) * LDC + wn * 64 + ni * 16,
                                    acc[mi][ni], LDC, wmma::mem_row_major);
}

// ---------------------------------------------------------------------------
// QKV projection + bias + RoPE fused epilogue -> fp16. grid (8, 32, 3).
// ---------------------------------------------------------------------------
__global__ void __launch_bounds__(256, 2)
qkv_mma(const float* __restrict__ bq,
        const float* __restrict__ bk,
        const float* __restrict__ bv)
{
    gdc_wait();   // PDL: conv_kernel outputs must be visible
    extern __shared__ char smraw[];
    const int tid = threadIdx.x, wid = tid >> 5;
    const int wm = wid & 3, wn = wid >> 2;
    const int m0 = blockIdx.y * 128, n0 = blockIdx.x * 128;
    const int z = blockIdx.z;

    const __half* W = g_wh + (size_t)z * HH;
    const float* bias = (z == 0) ? bq : (z == 1) ? bk : bv;
    __half* dst = (z == 0) ? g_q : (z == 1) ? g_k : g_v;

    HFragC acc[2][4];
    hgemm_mainloop(g_xh + (size_t)m0 * HIDDEN, W + (size_t)n0 * HIDDEN,
                   (__half*)smraw, acc, wm, wn);

    float* Cs = (float*)smraw;
    stage_C(Cs, acc, wm, wn);
    __syncthreads();

    const int r = tid >> 1, hh = tid & 1;
    const int m = m0 + r;
    const int b = m >> 11, s = m & (SEQ - 1);
    const int h = (n0 >> 6) + hh;
    const float* crow = Cs + r * LDC + hh * 64;
    const float* brow = bias + n0 + hh * 64;
    __half* drow = dst + (((size_t)(b * HEADS + h)) * SEQ + s) * HEAD_DIM;

    if (z < 2) {
        const float* rt = g_rt + s * 64;
        const float scale = (z == 0) ? 0.125f * 1.44269504088896f : 1.0f;
#pragma unroll
        for (int d0 = 0; d0 < 32; d0 += 4) {
            float4 x1 = *(const float4*)(crow + d0);
            float4 x2 = *(const float4*)(crow + d0 + 32);
            float4 b1 = *(const float4*)(brow + d0);
            float4 b2 = *(const float4*)(brow + d0 + 32);
            float4 cc = *(const float4*)(rt + d0);
            float4 ss = *(const float4*)(rt + 32 + d0);
            x1.x += b1.x; x1.y += b1.y; x1.z += b1.z; x1.w += b1.w;
            x2.x += b2.x; x2.y += b2.y; x2.z += b2.z; x2.w += b2.w;
            float o1x = (x1.x * cc.x - x2.x * ss.x) * scale;
            float o1y = (x1.y * cc.y - x2.y * ss.y) * scale;
            float o1z = (x1.z * cc.z - x2.z * ss.z) * scale;
            float o1w = (x1.w * cc.w - x2.w * ss.w) * scale;
            float o2x = (x2.x * cc.x + x1.x * ss.x) * scale;
            float o2y = (x2.y * cc.y + x1.y * ss.y) * scale;
            float o2z = (x2.z * cc.z + x1.z * ss.z) * scale;
            float o2w = (x2.w * cc.w + x1.w * ss.w) * scale;
            *(__half2*)(drow + d0)      = __floats2half2_rn(o1x, o1y);
            *(__half2*)(drow + d0 + 2)  = __floats2half2_rn(o1z, o1w);
            *(__half2*)(drow + d0 + 32) = __floats2half2_rn(o2x, o2y);
            *(__half2*)(drow + d0 + 34) = __floats2half2_rn(o2z, o2w);
        }
    } else {
#pragma unroll
        for (int d0 = 0; d0 < 64; d0 += 4) {
            float4 x = *(const float4*)(crow + d0);
            float4 bb = *(const float4*)(brow + d0);
            *(__half2*)(drow + d0)     = __floats2half2_rn(x.x + bb.x, x.y + bb.y);
            *(__half2*)(drow + d0 + 2) = __floats2half2_rn(x.z + bb.z, x.w + bb.w);
        }
    }
}

// ---------------------------------------------------------------------------
// Output projection + bias, 128x128 tiles. grid (8, 32).
// ---------------------------------------------------------------------------
__global__ void __launch_bounds__(256, 2)
out_mma(const float* __restrict__ bo, float* __restrict__ out)
{
    gdc_wait();   // PDL: flash_mma output (g_ao) must be visible
    extern __shared__ char smraw[];
    const int tid = threadIdx.x, wid = tid >> 5;
    const int wm = wid & 3, wn = wid >> 2;
    const int m0 = blockIdx.y * 128, n0 = blockIdx.x * 128;

    HFragC acc[2][4];
    hgemm_mainloop(g_ao + (size_t)m0 * HIDDEN,
                   g_wh + 3 * (size_t)HH + (size_t)n0 * HIDDEN,
                   (__half*)smraw, acc, wm, wn);

    float* Cs = (float*)smraw;
    stage_C(Cs, acc, wm, wn);
    __syncthreads();

    const int r = tid >> 1, half = tid & 1;
    const float* crow = Cs + r * LDC + half * 64;
    const float* brow = bo + n0 + half * 64;
    float* orow = out + (size_t)(m0 + r) * HIDDEN + n0 + half * 64;
#pragma unroll
    for (int j = 0; j < 64; j += 4) {
        float4 x = *(const float4*)(crow + j);
        float4 bb = *(const float4*)(brow + j);
        x.x += bb.x; x.y += bb.y; x.z += bb.z; x.w += bb.w;
        *(float4*)(orow + j) = x;
    }
}

// ---------------------------------------------------------------------------
// Flash attention fp16: mma.m16n8k16, ldmatrix.x4, register-resident P.
// Softmax: ex2.f16x2 + row-sums via ones-MMA (unconditional rescale).
// grid (SEQ/128, BHN), 256 threads / 8 warps; warp owns q-rows [wid*16,+16).
// K/V staged 128 keys at a time (double-buffered), two 64-key halves each.
// ---------------------------------------------------------------------------
#define FPH 72                    // halves; 144B row stride
#define KROWS 128                 // keys per stage
#define KVH (KROWS*FPH)           // halves per K (or V) stage
#define ONES_H2 0x3C003C00u       // (1.0h, 1.0h)

__global__ void __launch_bounds__(256, 2)
flash_mma()
{
    gdc_wait();   // PDL: qkv_mma outputs (g_q/g_k/g_v) must be visible
    extern __shared__ char smraw[];
    __half* KsB = (__half*)smraw;            // 2 stages [128][FPH]
    __half* VsB = KsB + 2 * KVH;             // 2 stages [128][FPH]

    const int tid = threadIdx.x, wid = tid >> 5, lane = tid & 31;
    const int g = lane >> 2, t = lane & 3;
    const int bh = blockIdx.y;
    const int q0 = blockIdx.x * 128;
    const int r0 = wid * 16;

    const int k4off = ((lane >> 4) * 8 + (lane & 7)) * FPH + ((lane >> 3) & 1) * 8;
    const int v4off = (((lane >> 3) & 1) * 8 + (lane & 7)) * FPH + (lane >> 4) * 8;

    const __half* q0p = g_q + ((size_t)(bh * SEQ + q0 + r0 + g)) * HEAD_DIM;
    const __half* q8p = q0p + 8 * HEAD_DIM;
    uint32_t qa[4][4];
#pragma unroll
    for (int kb = 0; kb < 4; kb++) {
        qa[kb][0] = *(const uint32_t*)(q0p + kb * 16 + 2 * t);
        qa[kb][1] = *(const uint32_t*)(q8p + kb * 16 + 2 * t);
        qa[kb][2] = *(const uint32_t*)(q0p + kb * 16 + 8 + 2 * t);
        qa[kb][3] = *(const uint32_t*)(q8p + kb * 16 + 8 + 2 * t);
    }

    float oacc[8][4];
#pragma unroll
    for (int nb = 0; nb < 8; nb++)
#pragma unroll
        for (int e = 0; e < 4; e++) oacc[nb][e] = 0.f;
    float mA = -1e30f, mB = -1e30f, lA = 0.f, lB = 0.f;

    const __half* kbase = g_k + (size_t)bh * SEQ * HEAD_DIM;
    const __half* vbase = g_v + (size_t)bh * SEQ * HEAD_DIM;
    auto issue = [&](int kt, int s) {
        __half* Kd = KsB + s * KVH;
        __half* Vd = VsB + s * KVH;
        const __half* ks = kbase + (size_t)kt * KROWS * HEAD_DIM;
        const __half* vs = vbase + (size_t)kt * KROWS * HEAD_DIM;
#pragma unroll
        for (int i = 0; i < 4; i++) {
            int idx = tid + i * 256;            // 0..1023
            int r = idx >> 3, c = (idx & 7) * 8;
            cp16(sm_u32(Kd + r * FPH + c), ks + r * 64 + c);
            cp16(sm_u32(Vd + r * FPH + c), vs + r * 64 + c);
        }
        cp_commit();
    };

    issue(0, 0);

    for (int kt = 0; kt < SEQ / KROWS; kt++) {
        int s = kt & 1;
        cp_wait0();
        __syncthreads();
        if (kt + 1 < SEQ / KROWS) issue(kt + 1, s ^ 1);

#pragma unroll
        for (int hlf = 0; hlf < 2; hlf++) {
            const uint32_t Ku = sm_u32(KsB + s * KVH + hlf * 64 * FPH);
            const uint32_t Vu = sm_u32(VsB + s * KVH + hlf * 64 * FPH);

            // ---- S = Q K^T (log2 domain) ----
            float sacc[8][4];
#pragma unroll
            for (int nb = 0; nb < 8; nb++)
#pragma unroll
                for (int e = 0; e < 4; e++) sacc[nb][e] = 0.f;

#pragma unroll
            for (int nb2 = 0; nb2 < 4; nb2++) {
#pragma unroll
                for (int kb = 0; kb < 4; kb++) {
                    uint32_t b0, b1, b2, b3;
                    ldsm_x4(b0, b1, b2, b3,
                            Ku + (uint32_t)(nb2 * 16 * FPH + kb * 16 + k4off) * 2);
                    mma16(sacc[2 * nb2],     qa[kb], b0, b1);
                    mma16(sacc[2 * nb2 + 1], qa[kb], b2, b3);
                }
            }

            // ---- row max ----
            float rmA = -1e30f, rmB = -1e30f;
#pragma unroll
            for (int nb = 0; nb < 8; nb++) {
                rmA = fmaxf(rmA, fmaxf(sacc[nb][0], sacc[nb][1]));
                rmB = fmaxf(rmB, fmaxf(sacc[nb][2], sacc[nb][3]));
            }
            rmA = fmaxf(rmA, __shfl_xor_sync(0xffffffffu, rmA, 1));
            rmA = fmaxf(rmA, __shfl_xor_sync(0xffffffffu, rmA, 2));
            rmB = fmaxf(rmB, __shfl_xor_sync(0xffffffffu, rmB, 1));
            rmB = fmaxf(rmB, __shfl_xor_sync(0xffffffffu, rmB, 2));

            float mnA = fmaxf(mA, rmA), mnB = fmaxf(mB, rmB);
            float aA = ex2(mA - mnA), aB = ex2(mB - mnB);

            // ---- P = 2^(S-m) fp16 pairs (ex2.f16x2); directly PV A-frags ----
            uint32_t pall[16];
#pragma unroll
            for (int nb = 0; nb < 8; nb++) {
                pall[2 * nb]     = ex2_h2(pack_h2(sacc[nb][0] - mnA, sacc[nb][1] - mnA));
                pall[2 * nb + 1] = ex2_h2(pack_h2(sacc[nb][2] - mnB, sacc[nb][3] - mnB));
            }

            // ---- row sums via ones-MMA (every lane gets the row sum) ----
            float rsum[4] = {0.f, 0.f, 0.f, 0.f};
#pragma unroll
            for (int kb2 = 0; kb2 < 4; kb2++)
                mma16(rsum, &pall[4 * kb2], ONES_H2, ONES_H2);

            lA = lA * aA + rsum[0];  mA = mnA;
            lB = lB * aB + rsum[2];  mB = mnB;
#pragma unroll
            for (int nb = 0; nb < 8; nb++) {
                oacc[nb][0] *= aA; oacc[nb][1] *= aA;
                oacc[nb][2] *= aB; oacc[nb][3] *= aB;
            }

            // ---- O += P V ----
#pragma unroll
            for (int kb2 = 0; kb2 < 4; kb2++) {
#pragma unroll
                for (int nb2 = 0; nb2 < 4; nb2++) {
                    uint32_t b0, b1, b2, b3;
                    ldsm_x4_t(b0, b1, b2, b3,
                              Vu + (uint32_t)(kb2 * 16 * FPH + v4off + nb2 * 16) * 2);
                    mma16(oacc[2 * nb2],     &pall[4 * kb2], b0, b1);
                    mma16(oacc[2 * nb2 + 1], &pall[4 * kb2], b2, b3);
                }
            }
        }
    }

    const int b = bh >> 4, h = bh & 15;
    float invA = 1.0f / lA, invB = 1.0f / lB;
    int rA = q0 + r0 + g, rB = rA + 8;
#pragma unroll
    for (int nb = 0; nb < 8; nb++) {
        int col = h * HEAD_DIM + nb * 8 + 2 * t;
        *(__half2*)&g_ao[((size_t)(b * SEQ + rA)) * HIDDEN + col] =
            __floats2half2_rn(oacc[nb][0] * invA, oacc[nb][1] * invA);
        *(__half2*)&g_ao[((size_t)(b * SEQ + rB)) * HIDDEN + col] =
            __floats2half2_rn(oacc[nb][2] * invB, oacc[nb][3] * invB);
    }
}

// ---------------------------------------------------------------------------
extern "C" void kernel_launch(void* const* d_in, const int* in_sizes, int n_in,
                              void* d_out, int out_size)
{
    const float* X  = (const float*)d_in[0];
    const float* Wq = (const float*)d_in[1];
    const float* bq = (const float*)d_in[2];
    const float* Wk = (const float*)d_in[3];
    const float* bk = (const float*)d_in[4];
    const float* Wv = (const float*)d_in[5];
    const float* bv = (const float*)d_in[6];
    const float* Wo = (const float*)d_in[7];
    const float* bo = (const float*)d_in[8];
    float* out = (float*)d_out;

    static const int GEMM_SMEM  = 4 * STGH * 2;       // 81920 (covers Cs 67584)
    static const int FLASH_SMEM = 4 * KVH * 2;        // 73728
    cudaFuncSetAttribute(qkv_mma,  cudaFuncAttributeMaxDynamicSharedMemorySize, GEMM_SMEM);
    cudaFuncSetAttribute(out_mma,  cudaFuncAttributeMaxDynamicSharedMemorySize, GEMM_SMEM);
    cudaFuncSetAttribute(flash_mma, cudaFuncAttributeMaxDynamicSharedMemorySize, FLASH_SMEM);

    conv_kernel<<<(CONVN8 + SEQ * 32) / 256, 256>>>(X, Wq, Wk, Wv, Wo);

    // PDL attribute: allow dependent kernels to launch while the predecessor
    // drains; consumers call griddepcontrol.wait before touching its data.
    cudaLaunchAttribute pdl;
    pdl.id = cudaLaunchAttributeProgrammaticStreamSerialization;
    pdl.val.programmaticStreamSerializationAllowed = 1;

    {
        cudaLaunchConfig_t cfg = {};
        cfg.gridDim = dim3(HIDDEN / 128, MTOT / 128, 3);
        cfg.blockDim = dim3(256, 1, 1);
        cfg.dynamicSmemBytes = GEMM_SMEM;
        cfg.attrs = &pdl;
        cfg.numAttrs = 1;
        cudaLaunchKernelEx(&cfg, qkv_mma, bq, bk, bv);
    }
    {
        cudaLaunchConfig_t cfg = {};
        cfg.gridDim = dim3(SEQ / 128, BHN, 1);
        cfg.blockDim = dim3(256, 1, 1);
        cfg.dynamicSmemBytes = FLASH_SMEM;
        cfg.attrs = &pdl;
        cfg.numAttrs = 1;
        cudaLaunchKernelEx(&cfg, flash_mma);
    }
    {
        cudaLaunchConfig_t cfg = {};
        cfg.gridDim = dim3(HIDDEN / 128, MTOT / 128, 1);
        cfg.blockDim = dim3(256, 1, 1);
        cfg.dynamicSmemBytes = GEMM_SMEM;
        cfg.attrs = &pdl;
        cfg.numAttrs = 1;
        cudaLaunchKernelEx(&cfg, out_mma, bo, out);
    }
}